// round 16
// baseline (speedup 1.0000x reference)
#include <cuda_runtime.h>
#include <cuda_bf16.h>
#include <cstdint>
#include <math.h>

// Problem constants (fixed by setup_inputs)
#define Bb    8
#define Hh    8
#define NSP   196
#define NTOK  3137
#define DIM   512
#define QKVD  1536
#define MROWS 25096        // Bb * NTOK

// -------------------- scratch (__device__ globals, alloc-free) --------------
// RULE (R4-R11): referenced ONLY from device code; never passed as kernel
// arguments from host (host shadow symbol + GB300 ATS = silent host write).
__device__ float         g_qkv [38547456];   // MROWS * QKVD fp32
__device__ __nv_bfloat16 g_xhi [12849152];
__device__ __nv_bfloat16 g_xlo [12849152];
__device__ __nv_bfloat16 g_ahi [12849152];
__device__ __nv_bfloat16 g_alo [12849152];
__device__ __nv_bfloat16 g_wqT_hi[786432];   // Wqkv^T [1536,512]
__device__ __nv_bfloat16 g_wqT_lo[786432];
__device__ __nv_bfloat16 g_woT_hi[262144];   // Wout^T [512,512]
__device__ __nv_bfloat16 g_woT_lo[262144];
__device__ float g_clsm[512];
__device__ float g_clss[512];
__device__ float g_clso[32768];

// -------------------- PTX helpers (sm_80-baseline only) ---------------------
__device__ __forceinline__ uint32_t smem_u32(const void* p) {
    uint32_t a;
    asm("{ .reg .u64 t; cvta.to.shared.u64 t, %1; cvt.u32.u64 %0, t; }"
        : "=r"(a) : "l"(p));
    return a;
}
__device__ __forceinline__ void cp_async16(uint32_t s, const void* g) {
    asm volatile("cp.async.cg.shared.global [%0], [%1], 16;"
                 :: "r"(s), "l"(g) : "memory");
}
#define CP_COMMIT() asm volatile("cp.async.commit_group;" ::: "memory")
#define CP_WAIT0()  asm volatile("cp.async.wait_group 0;" ::: "memory")

__device__ __forceinline__ void ldmx4(uint32_t* r, uint32_t addr) {
    asm volatile("ldmatrix.sync.aligned.m8n8.x4.shared.b16 {%0,%1,%2,%3}, [%4];"
                 : "=r"(r[0]), "=r"(r[1]), "=r"(r[2]), "=r"(r[3]) : "r"(addr));
}
__device__ __forceinline__ void mma_bf16(float* c, const uint32_t* a,
                                         uint32_t b0, uint32_t b1) {
    asm volatile(
        "mma.sync.aligned.m16n8k16.row.col.f32.bf16.bf16.f32 "
        "{%0,%1,%2,%3}, {%4,%5,%6,%7}, {%8,%9}, {%0,%1,%2,%3};"
        : "+f"(c[0]), "+f"(c[1]), "+f"(c[2]), "+f"(c[3])
        : "r"(a[0]), "r"(a[1]), "r"(a[2]), "r"(a[3]), "r"(b0), "r"(b1));
}
__device__ __forceinline__ void split_write(float v, __nv_bfloat16* hi,
                                            __nv_bfloat16* lo, size_t i) {
    __nv_bfloat16 h = __float2bfloat16(v);
    hi[i] = h;
    lo[i] = __float2bfloat16(v - __bfloat162float(h));
}

// -------------------- split x into hi/lo bf16 -------------------------------
__global__ __launch_bounds__(256)
void xsplit_kernel(const float* __restrict__ x) {
    size_t i = ((size_t)blockIdx.x * 256 + threadIdx.x) * 4;
    float4 v = *reinterpret_cast<const float4*>(x + i);
    split_write(v.x, g_xhi, g_xlo, i + 0);
    split_write(v.y, g_xhi, g_xlo, i + 1);
    split_write(v.z, g_xhi, g_xlo, i + 2);
    split_write(v.w, g_xhi, g_xlo, i + 3);
}

// ------------- transpose+split weights: W[K,N] -> T[N,K] (mode-selected) ----
__global__ __launch_bounds__(256)
void wsplit_kernel(const float* __restrict__ W, int K, int N, int mode) {
    __nv_bfloat16* Thi = (mode == 0) ? g_wqT_hi : g_woT_hi;
    __nv_bfloat16* Tlo = (mode == 0) ? g_wqT_lo : g_woT_lo;
    __shared__ float t[32][33];
    int n0 = blockIdx.x * 32, k0 = blockIdx.y * 32;
    int tx = threadIdx.x & 31, ty = threadIdx.x >> 5;   // 32 x 8
    #pragma unroll
    for (int i = 0; i < 4; i++) {
        int k = k0 + ty + i * 8;
        t[ty + i * 8][tx] = W[(size_t)k * N + n0 + tx];
    }
    __syncthreads();
    #pragma unroll
    for (int i = 0; i < 4; i++) {
        int n = n0 + ty + i * 8;
        float v = t[tx][ty + i * 8];
        split_write(v, Thi, Tlo, (size_t)n * K + k0 + tx);
    }
}

// -------------------- mma.sync GEMM (k-step 32, dynamic smem) ---------------
// C[M,Nc] = (Ahi+Alo) @ (Bhi+Blo)^T (+bias). 3-term mma, fp32 accum.
// 128x128 tile, k-step 32 (2 sub-steps of 16), double-buffered DYNAMIC smem
// = 73728 B total. Row pitch 144 B: [32 bf16 hi | 32 bf16 lo | 16B pad].
// ldmatrix phases over 8 rows @144B: banks 4r+{0..3} cover all 32 -> clean.
// 16 sync boundaries instead of 32: halves barrier/refill overhead.
#define ROWB   144
#define B_OFF  18432              // 128 rows * 144B
#define STAGEB 36864              // A + B
#define GSMEM  73728              // 2 stages

__global__ __launch_bounds__(256, 2)
void gemm_mma_kernel(const float* __restrict__ bias, float* __restrict__ Cext,
                     int M, int Nc, int mode)
{
    const __nv_bfloat16 *Ahi, *Alo, *Bh, *Bl;
    float* C;
    if (mode == 0) {
        Ahi = g_xhi; Alo = g_xlo; Bh = g_wqT_hi; Bl = g_wqT_lo;
        C = g_qkv;
    } else {
        Ahi = g_ahi; Alo = g_alo; Bh = g_woT_hi; Bl = g_woT_lo;
        C = Cext;
    }

    extern __shared__ __align__(16) uint32_t smem[];
    uint32_t sb = smem_u32(smem);

    const int tid = threadIdx.x, wid = tid >> 5, lane = tid & 31;
    const int warpM = wid >> 2, warpN = wid & 3;
    const int gq = lane >> 2, tq = lane & 3;
    const int rowBase = blockIdx.y * 128, colBase = blockIdx.x * 128;

    // staging: thread -> (row = tid>>1, k16-half = tid&1), 16 bf16 = 32B each
    const int srow = tid >> 1, skh = tid & 1;
    const int agr = min(rowBase + srow, M - 1);
    const size_t aoffg = (size_t)agr * DIM + skh * 16;
    const size_t boffg = (size_t)(colBase + srow) * DIM + skh * 16;
    const uint32_t soff = (uint32_t)srow * ROWB + (uint32_t)skh * 32;

    // ldmatrix lane addressing
    const int arow  = lane & 15;
    const uint32_t aksel = (uint32_t)(lane >> 4) * 16;
    const int brow  = lane & 7;
    const uint32_t bksel = (uint32_t)((lane >> 3) & 1) * 16;
    const int bnsel = lane >> 4;

    float acc[4][4][4];
    #pragma unroll
    for (int i = 0; i < 4; i++)
        #pragma unroll
        for (int j = 0; j < 4; j++)
            #pragma unroll
            for (int e = 0; e < 4; e++) acc[i][j][e] = 0.f;

    // prologue: stage 0 (8 cp.async of 16B per thread)
    {
        uint32_t st = sb;
        cp_async16(st + soff,               Ahi + aoffg);
        cp_async16(st + soff + 16,          Ahi + aoffg + 8);
        cp_async16(st + soff + 64,          Alo + aoffg);
        cp_async16(st + soff + 80,          Alo + aoffg + 8);
        cp_async16(st + soff + B_OFF,       Bh + boffg);
        cp_async16(st + soff + B_OFF + 16,  Bh + boffg + 8);
        cp_async16(st + soff + B_OFF + 64,  Bl + boffg);
        cp_async16(st + soff + B_OFF + 80,  Bl + boffg + 8);
    }
    CP_COMMIT();

    const int nIter = DIM / 32;   // 16
    for (int it = 0; it < nIter; it++) {
        CP_WAIT0();
        __syncthreads();          // buf(it&1) visible; prior reads done

        uint32_t stg = sb + (uint32_t)(it & 1) * STAGEB;
        uint32_t abase0 = stg + (uint32_t)(warpM * 64 + arow) * ROWB + aksel;
        uint32_t bbase0 = stg + B_OFF
                        + (uint32_t)(warpN * 32 + bnsel * 8 + brow) * ROWB
                        + bksel;

        #pragma unroll
        for (int ks = 0; ks < 2; ks++) {
            uint32_t abase = abase0 + (uint32_t)ks * 32;
            uint32_t bbase = bbase0 + (uint32_t)ks * 32;

            // B fragments (hi at +0, lo at +64)
            uint32_t bhf[2][4], blf[2][4];
            #pragma unroll
            for (int p = 0; p < 2; p++) {
                ldmx4(bhf[p], bbase + (uint32_t)p * (16 * ROWB));
                ldmx4(blf[p], bbase + (uint32_t)p * (16 * ROWB) + 64);
            }
            // A-hi fragments
            uint32_t af[4][4];
            #pragma unroll
            for (int mf = 0; mf < 4; mf++)
                ldmx4(af[mf], abase + (uint32_t)mf * (16 * ROWB));

            // issue next-stage copies once, early in the iter (ks==0)
            if (ks == 0) {
                if (it + 1 < nIter) {
                    uint32_t st = sb + (uint32_t)((it + 1) & 1) * STAGEB;
                    int k0 = (it + 1) * 32;
                    cp_async16(st + soff,              Ahi + aoffg + k0);
                    cp_async16(st + soff + 16,         Ahi + aoffg + k0 + 8);
                    cp_async16(st + soff + 64,         Alo + aoffg + k0);
                    cp_async16(st + soff + 80,         Alo + aoffg + k0 + 8);
                    cp_async16(st + soff + B_OFF,      Bh + boffg + k0);
                    cp_async16(st + soff + B_OFF + 16, Bh + boffg + k0 + 8);
                    cp_async16(st + soff + B_OFF + 64, Bl + boffg + k0);
                    cp_async16(st + soff + B_OFF + 80, Bl + boffg + k0 + 8);
                }
                CP_COMMIT();
            }

            // pass 1: Ahi*Bhi + Ahi*Blo
            #pragma unroll
            for (int mf = 0; mf < 4; mf++)
                #pragma unroll
                for (int nf = 0; nf < 4; nf++) {
                    int p = nf >> 1, q = nf & 1;
                    mma_bf16(acc[mf][nf], af[mf], bhf[p][q*2], bhf[p][q*2+1]);
                    mma_bf16(acc[mf][nf], af[mf], blf[p][q*2], blf[p][q*2+1]);
                }
            // pass 2: A-lo (reuse regs), Alo*Bhi
            #pragma unroll
            for (int mf = 0; mf < 4; mf++)
                ldmx4(af[mf], abase + (uint32_t)mf * (16 * ROWB) + 64);
            #pragma unroll
            for (int mf = 0; mf < 4; mf++)
                #pragma unroll
                for (int nf = 0; nf < 4; nf++) {
                    int p = nf >> 1, q = nf & 1;
                    mma_bf16(acc[mf][nf], af[mf], bhf[p][q*2], bhf[p][q*2+1]);
                }
        }
    }

    // epilogue: direct float2 stores (documented C fragment layout)
    #pragma unroll
    for (int nf = 0; nf < 4; nf++) {
        int col = colBase + warpN * 32 + nf * 8 + tq * 2;
        float2 bv = make_float2(0.f, 0.f);
        if (bias) bv = *reinterpret_cast<const float2*>(&bias[col]);
        #pragma unroll
        for (int mf = 0; mf < 4; mf++) {
            int r0 = rowBase + warpM * 64 + mf * 16 + gq;
            if (r0 < M) {
                float2 v = make_float2(acc[mf][nf][0] + bv.x,
                                       acc[mf][nf][1] + bv.y);
                *reinterpret_cast<float2*>(&C[(size_t)r0 * Nc + col]) = v;
            }
            int r1 = r0 + 8;
            if (r1 < M) {
                float2 v = make_float2(acc[mf][nf][2] + bv.x,
                                       acc[mf][nf][3] + bv.y);
                *reinterpret_cast<float2*>(&C[(size_t)r1 * Nc + col]) = v;
            }
        }
    }
}

// -------------------- CLS attention: chunked partials + merge ---------------
#define CLS_CH 393     // ceil(3137/8)

__global__ __launch_bounds__(256)
void cls_partial_kernel()
{
    __shared__ float sq[64];
    __shared__ float sc[CLS_CH];
    __shared__ float red[256];

    const int bx = blockIdx.x;           // bh*8 + c
    const int bh = bx >> 3, c = bx & 7;
    const int b = bh / Hh, h = bh % Hh;
    const int tid = threadIdx.x;
    const float scale = 0.125f;
    const int t0 = c * CLS_CH, t1 = min(NTOK, t0 + CLS_CH);

    if (tid < 64)
        sq[tid] = g_qkv[(size_t)(b * NTOK) * QKVD + h * 64 + tid] * scale;
    __syncthreads();

    float lmax = -1e30f;
    for (int t = t0 + tid; t < t1; t += 256) {
        const float4* kp = reinterpret_cast<const float4*>(
            &g_qkv[(size_t)(b * NTOK + t) * QKVD + DIM + h * 64]);
        float d0 = 0.f, d1 = 0.f, d2 = 0.f, d3 = 0.f;
        #pragma unroll
        for (int i = 0; i < 16; i++) {
            float4 kv = kp[i];
            d0 += sq[4*i+0] * kv.x; d1 += sq[4*i+1] * kv.y;
            d2 += sq[4*i+2] * kv.z; d3 += sq[4*i+3] * kv.w;
        }
        float dot = (d0 + d1) + (d2 + d3);
        sc[t - t0] = dot;
        lmax = fmaxf(lmax, dot);
    }
    red[tid] = lmax; __syncthreads();
    for (int s = 128; s > 0; s >>= 1) {
        if (tid < s) red[tid] = fmaxf(red[tid], red[tid + s]);
        __syncthreads();
    }
    const float m = red[0];
    __syncthreads();

    float lsum = 0.f;
    for (int t = t0 + tid; t < t1; t += 256) {
        float e = expf(sc[t - t0] - m);
        sc[t - t0] = e;
        lsum += e;
    }
    red[tid] = lsum; __syncthreads();
    for (int s = 128; s > 0; s >>= 1) {
        if (tid < s) red[tid] += red[tid + s];
        __syncthreads();
    }
    const float ssum = red[0];
    __syncthreads();

    const int d = tid & 63, chunk = tid >> 6;
    float acc = 0.f;
    for (int t = t0 + chunk; t < t1; t += 4)
        acc += sc[t - t0] * g_qkv[(size_t)(b * NTOK + t) * QKVD + 2 * DIM + h * 64 + d];
    red[tid] = acc; __syncthreads();
    if (chunk == 0) {
        float tot = acc + red[tid + 64] + red[tid + 128] + red[tid + 192];
        g_clso[bx * 64 + d] = tot;
        if (d == 0) { g_clsm[bx] = m; g_clss[bx] = ssum; }
    }
}

__global__ __launch_bounds__(64)
void cls_merge_kernel()
{
    const int bh = blockIdx.x;
    const int b = bh / Hh, h = bh % Hh;
    const int d = threadIdx.x;

    float M = -1e30f;
    #pragma unroll
    for (int c = 0; c < 8; c++) M = fmaxf(M, g_clsm[bh * 8 + c]);
    float S = 0.f, O = 0.f;
    #pragma unroll
    for (int c = 0; c < 8; c++) {
        float w = expf(g_clsm[bh * 8 + c] - M);
        S += g_clss[bh * 8 + c] * w;
        O += g_clso[(bh * 8 + c) * 64 + d] * w;
    }
    split_write(O / S, g_ahi, g_alo, (size_t)(b * NTOK) * DIM + h * 64 + d);
}

// -------------------- time attention (float4 + 2q per pass) -----------------
__global__ __launch_bounds__(128)
void time_attn_kernel()
{
    __shared__ __align__(16) float Qs[16][68];
    __shared__ __align__(16) float Ks[17][68];
    __shared__ __align__(16) float Vs[17][68];

    const int s  = blockIdx.x;
    const int bh = s / NSP, j = s % NSP;
    const int b  = bh / Hh, h = bh % Hh;
    const int tid = threadIdx.x;
    const float scale = 0.125f;

    for (int idx = tid; idx < 16 * 16; idx += 128) {
        int i = idx >> 4, d4 = (idx & 15) * 4;
        int t = 1 + i * NSP + j;
        float4 q = *reinterpret_cast<const float4*>(
            &g_qkv[(size_t)(b * NTOK + t) * QKVD + h * 64 + d4]);
        q.x *= scale; q.y *= scale; q.z *= scale; q.w *= scale;
        *reinterpret_cast<float4*>(&Qs[i][d4]) = q;
    }
    for (int idx = tid; idx < 17 * 16; idx += 128) {
        int key = idx >> 4, d4 = (idx & 15) * 4;
        int t = (key == 0) ? 0 : 1 + (key - 1) * NSP + j;
        size_t base = (size_t)(b * NTOK + t) * QKVD + h * 64 + d4;
        *reinterpret_cast<float4*>(&Ks[key][d4]) =
            *reinterpret_cast<const float4*>(&g_qkv[base + DIM]);
        *reinterpret_cast<float4*>(&Vs[key][d4]) =
            *reinterpret_cast<const float4*>(&g_qkv[base + 2 * DIM]);
    }
    __syncthreads();

    const int w = tid >> 5, lane = tid & 31;
    #pragma unroll
    for (int pass = 0; pass < 2; pass++) {
        const int q0 = w * 2 + pass * 8, q1 = q0 + 1;
        float s0 = -1e30f, s1 = -1e30f;
        if (lane < 17) {
            float a0 = 0.f, a1 = 0.f;
            #pragma unroll
            for (int dd = 0; dd < 16; dd++) {
                float4 kv = *reinterpret_cast<const float4*>(&Ks[lane][dd * 4]);
                float4 qa = *reinterpret_cast<const float4*>(&Qs[q0][dd * 4]);
                float4 qb = *reinterpret_cast<const float4*>(&Qs[q1][dd * 4]);
                a0 += qa.x*kv.x + qa.y*kv.y + qa.z*kv.z + qa.w*kv.w;
                a1 += qb.x*kv.x + qb.y*kv.y + qb.z*kv.z + qb.w*kv.w;
            }
            s0 = a0; s1 = a1;
        }
        float m0 = s0, m1 = s1;
        #pragma unroll
        for (int o = 16; o > 0; o >>= 1) {
            m0 = fmaxf(m0, __shfl_xor_sync(0xffffffffu, m0, o));
            m1 = fmaxf(m1, __shfl_xor_sync(0xffffffffu, m1, o));
        }
        float e0 = (lane < 17) ? expf(s0 - m0) : 0.f;
        float e1 = (lane < 17) ? expf(s1 - m1) : 0.f;
        float t0 = e0, t1 = e1;
        #pragma unroll
        for (int o = 16; o > 0; o >>= 1) {
            t0 += __shfl_xor_sync(0xffffffffu, t0, o);
            t1 += __shfl_xor_sync(0xffffffffu, t1, o);
        }
        float p0 = e0 / t0, p1 = e1 / t1;

        float a00 = 0.f, a01 = 0.f, a10 = 0.f, a11 = 0.f;
        #pragma unroll
        for (int kk = 0; kk < 17; kk++) {
            float pj0 = __shfl_sync(0xffffffffu, p0, kk);
            float pj1 = __shfl_sync(0xffffffffu, p1, kk);
            float v0 = Vs[kk][lane], v1 = Vs[kk][lane + 32];
            a00 += pj0 * v0; a01 += pj0 * v1;
            a10 += pj1 * v0; a11 += pj1 * v1;
        }
        {
            int t = 1 + q0 * NSP + j;
            size_t ob = (size_t)(b * NTOK + t) * DIM + h * 64;
            split_write(a00, g_ahi, g_alo, ob + lane);
            split_write(a01, g_ahi, g_alo, ob + lane + 32);
        }
        {
            int t = 1 + q1 * NSP + j;
            size_t ob = (size_t)(b * NTOK + t) * DIM + h * 64;
            split_write(a10, g_ahi, g_alo, ob + lane);
            split_write(a11, g_ahi, g_alo, ob + lane + 32);
        }
    }
}

// -------------------- launch -----------------------------------------------
extern "C" void kernel_launch(void* const* d_in, const int* in_sizes, int n_in,
                              void* d_out, int out_size)
{
    const float* x    = (const float*)d_in[0];   // [B, N, 512]
    const float* Wqkv = (const float*)d_in[1];   // [512, 1536]
    const float* Wout = (const float*)d_in[2];   // [512, 512]
    const float* bout = (const float*)d_in[3];   // [512]
    float* out = (float*)d_out;

    cudaFuncSetAttribute(gemm_mma_kernel,
                         cudaFuncAttributeMaxDynamicSharedMemorySize, GSMEM);

    // 0) pre-split inputs/weights (globals selected inside kernels)
    xsplit_kernel<<<(MROWS * DIM) / 1024, 256>>>(x);
    {
        dim3 g1(QKVD / 32, DIM / 32);
        wsplit_kernel<<<g1, 256>>>(Wqkv, DIM, QKVD, 0);
        dim3 g2(DIM / 32, DIM / 32);
        wsplit_kernel<<<g2, 256>>>(Wout, DIM, DIM, 1);
    }
    // 1) qkv = x @ Wqkv -> g_qkv
    {
        dim3 grid(QKVD / 128, (MROWS + 127) / 128);
        gemm_mma_kernel<<<grid, 256, GSMEM>>>(nullptr, nullptr, MROWS, QKVD, 0);
    }
    // 2) attention -> g_ahi/g_alo
    cls_partial_kernel<<<512, 256>>>();
    cls_merge_kernel<<<Bb * Hh, 64>>>();
    time_attn_kernel<<<Bb * Hh * NSP, 128>>>();
    // 3) out = attn @ Wout + bias
    {
        dim3 grid(DIM / 128, (MROWS + 127) / 128);
        gemm_mma_kernel<<<grid, 256, GSMEM>>>(bout, out, MROWS, DIM, 1);
    }
}